// round 14
// baseline (speedup 1.0000x reference)
#include <cuda_runtime.h>
#include <cuda_fp16.h>
#include <cstdint>

// ---------------------------------------------------------------------------
// Problem constants
// ---------------------------------------------------------------------------
#define DIMC      256
#define HEADS     8
#define HEAD_DIM  32
#define HIDDEN    1024
#define SEQ       2048
#define BATCH     2
#define RPS       (BATCH * SEQ)          // 4096 rows per stream
#define TOTAL_ROWS (2 * RPS)             // 8192
#define STREAM_OFF (RPS * DIMC)

// HEAD_DIM^-0.25 * sqrt(log2(e)) : scores come out in log2-units
#define QK_SCALE_L2 (0.42044820762685725f * 1.2011224087864498f)
#define ONES_H2 0x3C003C00u

// ---------------------------------------------------------------------------
// Scratch
// ---------------------------------------------------------------------------
__device__ __half g_n  [TOTAL_ROWS * DIMC];       // LN1 out
__device__ __half g_qk [TOTAL_ROWS * DIMC];       // log2-scaled
__device__ __half g_v  [TOTAL_ROWS * DIMC];
__device__ __half g_m  [TOTAL_ROWS * DIMC];       // flash out
__device__ __half g_cat[TOTAL_ROWS * 2 * DIMC];   // [h(x) | h(merge)]
__device__ __half g_h  [TOTAL_ROWS * HIDDEN];     // fc1 out
__device__ float  g_t  [TOTAL_ROWS * DIMC];       // fc2 out (fp32 for LN2)

__device__ __half g_wqk[DIMC * DIMC];
__device__ __half g_wv [DIMC * DIMC];
__device__ __half g_wm [DIMC * DIMC];
__device__ __half g_wf1[HIDDEN * 2 * DIMC];
__device__ __half g_wf2[DIMC * HIDDEN];

// ---------------------------------------------------------------------------
// PTX helpers
// ---------------------------------------------------------------------------
__device__ __forceinline__ void mma_f16(
    float& c0, float& c1, float& c2, float& c3,
    uint32_t a0, uint32_t a1, uint32_t a2, uint32_t a3,
    uint32_t b0, uint32_t b1)
{
    asm volatile(
        "mma.sync.aligned.m16n8k16.row.col.f32.f16.f16.f32 "
        "{%0,%1,%2,%3},{%4,%5,%6,%7},{%8,%9},{%0,%1,%2,%3};"
        : "+f"(c0), "+f"(c1), "+f"(c2), "+f"(c3)
        : "r"(a0), "r"(a1), "r"(a2), "r"(a3), "r"(b0), "r"(b1));
}

__device__ __forceinline__ uint32_t smem_u32(const void* p) {
    return (uint32_t)__cvta_generic_to_shared(p);
}
__device__ __forceinline__ void cp_async16(uint32_t dst, const void* src) {
    asm volatile("cp.async.cg.shared.global [%0], [%1], 16;"
                 :: "r"(dst), "l"(src));
}
__device__ __forceinline__ void cp_commit() {
    asm volatile("cp.async.commit_group;");
}
template <int N>
__device__ __forceinline__ void cp_wait() {
    asm volatile("cp.async.wait_group %0;" :: "n"(N));
}
__device__ __forceinline__ void ldsm_x4(uint32_t& r0, uint32_t& r1,
                                        uint32_t& r2, uint32_t& r3,
                                        uint32_t addr) {
    asm volatile("ldmatrix.sync.aligned.m8n8.x4.shared.b16 {%0,%1,%2,%3}, [%4];"
                 : "=r"(r0), "=r"(r1), "=r"(r2), "=r"(r3) : "r"(addr));
}
__device__ __forceinline__ void ldsm_x4_trans(uint32_t& r0, uint32_t& r1,
                                              uint32_t& r2, uint32_t& r3,
                                              uint32_t addr) {
    asm volatile("ldmatrix.sync.aligned.m8n8.x4.trans.shared.b16 {%0,%1,%2,%3}, [%4];"
                 : "=r"(r0), "=r"(r1), "=r"(r2), "=r"(r3) : "r"(addr));
}
__device__ __forceinline__ uint32_t h2u(float a, float b) {
    __half2 h = __floats2half2_rn(a, b);
    return *reinterpret_cast<uint32_t*>(&h);
}
__device__ __forceinline__ uint32_t hadd2u(uint32_t a, uint32_t b) {
    uint32_t r;
    asm("add.f16x2 %0, %1, %2;" : "=r"(r) : "r"(a), "r"(b));
    return r;
}
// pack (lo,hi) to f16x2 then exp2 both halves
__device__ __forceinline__ uint32_t exp2_h2(float lo, float hi) {
    uint32_t r;
    asm("{\n\t.reg .b32 t;\n\t"
        "cvt.rn.f16x2.f32 t, %2, %1;\n\t"
        "ex2.approx.f16x2 %0, t;\n\t}"
        : "=r"(r) : "f"(lo), "f"(hi));
    return r;
}
__device__ __forceinline__ float exp2_f32(float x) {
    float y;
    asm("ex2.approx.ftz.f32 %0, %1;" : "=f"(y) : "f"(x));
    return y;
}

// ---------------------------------------------------------------------------
// Fused: weight conversion fp32->fp16 (blocks 0..1919) + LayerNorm over both
// streams (blocks 1920..2943, one warp per row). Independent work, one launch.
// ---------------------------------------------------------------------------
#define CVT_BLOCKS 1920
#define LN_BLOCKS  (TOTAL_ROWS / 8)

__global__ __launch_bounds__(256) void ln_cvt_kernel(
    const float* __restrict__ x0, const float* __restrict__ x1,
    const float* __restrict__ w, const float* __restrict__ b,
    const float* __restrict__ qk_w, const float* __restrict__ v_w,
    const float* __restrict__ mw,   const float* __restrict__ f1w,
    const float* __restrict__ f2w,
    __half* __restrict__ out, __half* __restrict__ cat)
{
    int bx = blockIdx.x;
    if (bx < CVT_BLOCKS) {
        int i = bx * 256 + threadIdx.x;
        const float2* s; __half2* d; int off;
        if      (i <  32768) { s = (const float2*)qk_w; d = (__half2*)g_wqk; off = i; }
        else if (i <  65536) { s = (const float2*)v_w;  d = (__half2*)g_wv;  off = i -  32768; }
        else if (i <  98304) { s = (const float2*)mw;   d = (__half2*)g_wm;  off = i -  65536; }
        else if (i < 360448) { s = (const float2*)f1w;  d = (__half2*)g_wf1; off = i -  98304; }
        else                 { s = (const float2*)f2w;  d = (__half2*)g_wf2; off = i - 360448; }
        float2 f = s[off];
        d[off] = __floats2half2_rn(f.x, f.y);
        return;
    }
    int warp = threadIdx.x >> 5, lane = threadIdx.x & 31;
    int row = (bx - CVT_BLOCKS) * 8 + warp;
    const float* xr = (row < RPS) ? x0 + (size_t)row * DIMC
                                  : x1 + (size_t)(row - RPS) * DIMC;
    float v[8];
    float sum = 0.f;
#pragma unroll
    for (int i = 0; i < 8; i++) { v[i] = xr[lane + i * 32]; sum += v[i]; }
#pragma unroll
    for (int o = 16; o; o >>= 1) sum += __shfl_xor_sync(0xffffffffu, sum, o);
    float mean = sum * (1.f / 256.f);
    float vs = 0.f;
#pragma unroll
    for (int i = 0; i < 8; i++) { float d = v[i] - mean; vs += d * d; }
#pragma unroll
    for (int o = 16; o; o >>= 1) vs += __shfl_xor_sync(0xffffffffu, vs, o);
    float rstd = rsqrtf(vs * (1.f / 256.f) + 1e-5f);
    __half* orow = out + (size_t)row * DIMC;
    __half* crow = cat + (size_t)row * (2 * DIMC);
#pragma unroll
    for (int i = 0; i < 8; i++) {
        int c = lane + i * 32;
        orow[c] = __float2half_rn((v[i] - mean) * rstd * w[c] + b[c]);
        crow[c] = __float2half_rn(v[i]);
    }
}

// ---------------------------------------------------------------------------
// Final: out = x + gamma * LayerNorm(t)
// ---------------------------------------------------------------------------
__global__ __launch_bounds__(256) void final_kernel(
    const float* __restrict__ t,
    const float* __restrict__ x0, const float* __restrict__ x1,
    const float* __restrict__ w, const float* __restrict__ b,
    const float* __restrict__ gamma, float* __restrict__ out)
{
    int warp = threadIdx.x >> 5, lane = threadIdx.x & 31;
    int row = blockIdx.x * 8 + warp;
    const float* tr = t + (size_t)row * DIMC;
    const float* xr = (row < RPS) ? x0 + (size_t)row * DIMC
                                  : x1 + (size_t)(row - RPS) * DIMC;
    float v[8];
    float sum = 0.f;
#pragma unroll
    for (int i = 0; i < 8; i++) { v[i] = tr[lane + i * 32]; sum += v[i]; }
#pragma unroll
    for (int o = 16; o; o >>= 1) sum += __shfl_xor_sync(0xffffffffu, sum, o);
    float mean = sum * (1.f / 256.f);
    float vs = 0.f;
#pragma unroll
    for (int i = 0; i < 8; i++) { float d = v[i] - mean; vs += d * d; }
#pragma unroll
    for (int o = 16; o; o >>= 1) vs += __shfl_xor_sync(0xffffffffu, vs, o);
    float rstd = rsqrtf(vs * (1.f / 256.f) + 1e-5f);
    float* orow = out + (size_t)row * DIMC;
#pragma unroll
    for (int i = 0; i < 8; i++) {
        int c = lane + i * 32;
        float ln = (v[i] - mean) * rstd * w[c] + b[c];
        orow[c] = xr[c] + gamma[c] * ln;
    }
}

// ---------------------------------------------------------------------------
// cp.async 3-stage fp16 GEMM, ldmatrix fragment loads. (unchanged from R13)
// BM=128, BN=128, BK=32, 256 threads (8 warps 2x4), warp tile 64x32, m16n8k16.
// ---------------------------------------------------------------------------
#define GEMM_SMEM (3 * (128 + 128) * 40 * 2)

template <bool GELU, bool HAS_BIAS, bool DUAL, bool HALF_OUT>
__global__ __launch_bounds__(256, 2) void gemm_tc(
    const __half* __restrict__ A0,
    const __half* __restrict__ B0, const __half* __restrict__ B1,
    const float* __restrict__ bias,
    void* __restrict__ C0, void* __restrict__ C1,
    int Nout, int K, int ldC, float alpha0, float alpha1)
{
    constexpr int BK = 32;
    extern __shared__ __half dsm[];
    __half* AsBase = dsm;                    // [3][128][40]
    __half* BsBase = dsm + 3 * 128 * 40;     // [3][128][40]

    int tid = threadIdx.x;
    int wid = tid >> 5, lane = tid & 31;
    int grp = lane >> 2, tig = lane & 3;
    int lm = lane >> 3, lr = lane & 7;
    int warp_m = wid >> 2, warp_n = wid & 3;
    int m0 = blockIdx.y * 128;
    int n0 = blockIdx.x * 128;

    int a_row = warp_m * 64 + (lm & 1) * 8 + lr;
    int a_col = (lm >> 1) * 8;
    int b_row = warp_n * 32 + (lm >> 1) * 8 + lr;
    int b_col = (lm & 1) * 8;

    const __half* Bp;
    void* Cp;
    float alpha;
    if (DUAL) {
        if (n0 < Nout) { Bp = B0 + (size_t)n0 * K; Cp = C0; alpha = alpha0; }
        else { n0 -= Nout; Bp = B1 + (size_t)n0 * K; Cp = C1; alpha = alpha1; }
    } else {
        Bp = B0 + (size_t)n0 * K; Cp = C0; alpha = alpha0;
    }

    float acc[4][4][4] = {};
    int KT = K / BK;

    auto load_stage = [&](int ktb, int s) {
        __half* Ad = AsBase + s * (128 * 40);
        __half* Bd = BsBase + s * (128 * 40);
#pragma unroll
        for (int j = 0; j < 2; j++) {
            int idx = tid + j * 256;
            int r = idx >> 2, c = idx & 3;
            cp_async16(smem_u32(&Ad[r * 40 + c * 8]),
                       A0 + (size_t)(m0 + r) * K + ktb + c * 8);
        }
#pragma unroll
        for (int j = 0; j < 2; j++) {
            int idx = tid + j * 256;
            int r = idx >> 2, c = idx & 3;
            cp_async16(smem_u32(&Bd[r * 40 + c * 8]),
                       Bp + (size_t)r * K + ktb + c * 8);
        }
        cp_commit();
    };

    load_stage(0, 0);
    if (KT > 1) load_stage(BK, 1);
    else        cp_commit();

    int s = 0, sl = 2;
    for (int kt = 0; kt < KT; kt++) {
        if (kt + 2 < KT) {
            load_stage((kt + 2) * BK, sl);
            cp_wait<2>();
        } else if (kt + 1 < KT) {
            cp_wait<1>();
        } else {
            cp_wait<0>();
        }
        __syncthreads();

        const __half* Ad = AsBase + s * (128 * 40);
        const __half* Bd = BsBase + s * (128 * 40);
#pragma unroll
        for (int kc = 0; kc < 2; kc++) {
            uint32_t af[4][4], bf[4][2];
#pragma unroll
            for (int mt = 0; mt < 4; mt++)
                ldsm_x4(af[mt][0], af[mt][1], af[mt][2], af[mt][3],
                        smem_u32(Ad + (a_row + mt * 16) * 40 + a_col + kc * 16));
#pragma unroll
            for (int p = 0; p < 2; p++) {
                uint32_t r0, r1, r2, r3;
                ldsm_x4(r0, r1, r2, r3,
                        smem_u32(Bd + (b_row + p * 16) * 40 + b_col + kc * 16));
                bf[2 * p][0] = r0; bf[2 * p][1] = r1;
                bf[2 * p + 1][0] = r2; bf[2 * p + 1][1] = r3;
            }
#pragma unroll
            for (int mt = 0; mt < 4; mt++)
#pragma unroll
                for (int nt = 0; nt < 4; nt++)
                    mma_f16(acc[mt][nt][0], acc[mt][nt][1],
                            acc[mt][nt][2], acc[mt][nt][3],
                            af[mt][0], af[mt][1], af[mt][2], af[mt][3],
                            bf[nt][0], bf[nt][1]);
        }
        __syncthreads();
        s = (s == 2) ? 0 : s + 1;
        sl = (sl == 2) ? 0 : sl + 1;
    }

#pragma unroll
    for (int mt = 0; mt < 4; mt++) {
        int mr = m0 + warp_m * 64 + mt * 16;
#pragma unroll
        for (int nt = 0; nt < 4; nt++) {
            int nc = n0 + warp_n * 32 + nt * 8 + 2 * tig;
            float b0 = 0.f, b1 = 0.f;
            if (HAS_BIAS) { b0 = bias[nc]; b1 = bias[nc + 1]; }
            float v0 = acc[mt][nt][0] * alpha + b0;
            float v1 = acc[mt][nt][1] * alpha + b1;
            float v2 = acc[mt][nt][2] * alpha + b0;
            float v3 = acc[mt][nt][3] * alpha + b1;
            if (GELU) {
                v0 = 0.5f * v0 * (1.f + erff(v0 * 0.70710678118654752f));
                v1 = 0.5f * v1 * (1.f + erff(v1 * 0.70710678118654752f));
                v2 = 0.5f * v2 * (1.f + erff(v2 * 0.70710678118654752f));
                v3 = 0.5f * v3 * (1.f + erff(v3 * 0.70710678118654752f));
            }
            if (HALF_OUT) {
                uint32_t* Ch = (uint32_t*)Cp;
                Ch[((size_t)(mr + grp    ) * ldC + nc) >> 1] = h2u(v0, v1);
                Ch[((size_t)(mr + grp + 8) * ldC + nc) >> 1] = h2u(v2, v3);
            } else {
                float* Cf = (float*)Cp;
                *reinterpret_cast<float2*>(&Cf[(size_t)(mr + grp) * ldC + nc]) =
                    make_float2(v0, v1);
                *reinterpret_cast<float2*>(&Cf[(size_t)(mr + grp + 8) * ldC + nc]) =
                    make_float2(v2, v3);
            }
        }
    }
}

// ---------------------------------------------------------------------------
// fp16 flash attention: 16 queries/warp, register-resident P, exp2 softmax,
// l via pre-summed P fragments + single ones-mma, V via ldmatrix.x4.trans,
// 3-stage cp.async K/V pipeline with ONE __syncthreads per chunk
// (order: wait -> sync -> issue load(kc+2) -> compute).
// Block: 256 threads (8 warps), 128 queries, key chunks of 64.
// smem: K [3][64][40]h + V [3][64][40]h = 30720 B.
// ---------------------------------------------------------------------------
#define FLASH_SMEM ((3*64*40 + 3*64*40) * 2)

__global__ __launch_bounds__(256, 2) void flash_tc(
    const __half* __restrict__ qkb, const __half* __restrict__ vb,
    __half* __restrict__ mb)
{
    extern __shared__ __half dsm[];
    __half* KsB = dsm;                       // [3][64][40]
    __half* VsB = dsm + 3 * 64 * 40;         // [3][64][40]

    int tid = threadIdx.x;
    int wid = tid >> 5, lane = tid & 31;
    int grp = lane >> 2, tig = lane & 3;
    int lm = lane >> 3, lr = lane & 7;
    int h = blockIdx.y;
    int z = blockIdx.z;
    int b = z & 1, dir = z >> 1;

    const __half* Q  = dir ? qkb + STREAM_OFF : qkb;
    const __half* Kp = dir ? qkb : qkb + STREAM_OFF;
    const __half* Vp = dir ? vb  : vb  + STREAM_OFF;
    __half*       O  = dir ? mb + STREAM_OFF : mb;

    size_t brow = (size_t)b * SEQ;
    int q0 = blockIdx.x * 128 + wid * 16;

    // ldmatrix lane addressing
    int k_row = (lm >> 1) * 8 + lr;          // K: + p*16 ; col (lm&1)*8 + kk*16
    int k_col = (lm & 1) * 8;
    int v_row = (lm & 1) * 8 + lr;           // V trans: + kk*16 ; col (lm>>1)*8
    int v_col = (lm >> 1) * 8;

    // register-resident Q fragments: 2 k16-chunks over dh=32
    uint32_t qa[2][4];
    const uint32_t* Qu = reinterpret_cast<const uint32_t*>(
        Q + (brow + q0) * DIMC + h * HEAD_DIM);
#pragma unroll
    for (int kc = 0; kc < 2; kc++) {
        qa[kc][0] = Qu[(grp    ) * 128 + kc * 8 + tig    ];
        qa[kc][1] = Qu[(grp + 8) * 128 + kc * 8 + tig    ];
        qa[kc][2] = Qu[(grp    ) * 128 + kc * 8 + tig + 4];
        qa[kc][3] = Qu[(grp + 8) * 128 + kc * 8 + tig + 4];
    }

    auto load_chunk = [&](int kc, int s) {
        __half* Kd = KsB + s * (64 * 40);
        __half* Vd = VsB + s * (64 * 40);
        int r = tid >> 2, c = tid & 3;
        size_t g = (brow + (size_t)kc * 64 + r) * DIMC + h * HEAD_DIM + c * 8;
        cp_async16(smem_u32(&Kd[r * 40 + c * 8]), Kp + g);
        cp_async16(smem_u32(&Vd[r * 40 + c * 8]), Vp + g);
        cp_commit();
    };

    float oacc[4][4] = {};
    float lacc[4] = {};
    float mr0 = -1e30f, mr1 = -1e30f;
    constexpr int NC = SEQ / 64;

    load_chunk(0, 0);
    load_chunk(1, 1);

    int s = 0, sl = 2;
    for (int kc = 0; kc < NC; kc++) {
        if (kc + 1 < NC) cp_wait<1>();
        else             cp_wait<0>();
        __syncthreads();
        if (kc + 2 < NC) load_chunk(kc + 2, sl);

        const __half* Kd = KsB + s * (64 * 40);
        const __half* Vd = VsB + s * (64 * 40);

        // S = Q @ K^T : scores in log2 units (scale baked into qk)
        float sf[8][4] = {};
#pragma unroll
        for (int kk = 0; kk < 2; kk++) {
            uint32_t bf[8][2];
#pragma unroll
            for (int p = 0; p < 4; p++) {
                uint32_t r0, r1, r2, r3;
                ldsm_x4(r0, r1, r2, r3,
                        smem_u32(Kd + (k_row + p * 16) * 40 + k_col + kk * 16));
                bf[2 * p][0] = r0; bf[2 * p][1] = r1;
                bf[2 * p + 1][0] = r2; bf[2 * p + 1][1] = r3;
            }
#pragma unroll
            for (int nt = 0; nt < 8; nt++)
                mma_f16(sf[nt][0], sf[nt][1], sf[nt][2], sf[nt][3],
                        qa[kk][0], qa[kk][1], qa[kk][2], qa[kk][3],
                        bf[nt][0], bf[nt][1]);
        }

        // online softmax (log2 domain)
        float cm0 = -1e30f, cm1 = -1e30f;
#pragma unroll
        for (int nt = 0; nt < 8; nt++) {
            cm0 = fmaxf(cm0, fmaxf(sf[nt][0], sf[nt][1]));
            cm1 = fmaxf(cm1, fmaxf(sf[nt][2], sf[nt][3]));
        }
        cm0 = fmaxf(cm0, __shfl_xor_sync(0xffffffffu, cm0, 1));
        cm0 = fmaxf(cm0, __shfl_xor_sync(0xffffffffu, cm0, 2));
        cm1 = fmaxf(cm1, __shfl_xor_sync(0xffffffffu, cm1, 1));
        cm1 = fmaxf(cm1, __shfl_xor_sync(0xffffffffu, cm1, 2));
        float nm0 = fmaxf(mr0, cm0), nm1 = fmaxf(mr1, cm1);
        float corr0 = exp2_f32(mr0 - nm0), corr1 = exp2_f32(mr1 - nm1);
        mr0 = nm0; mr1 = nm1;

        // P = exp2(s - m) straight into PV A-fragments (C-frag == A-frag layout)
        uint32_t pa[4][4];
#pragma unroll
        for (int kk = 0; kk < 4; kk++) {
            pa[kk][0] = exp2_h2(sf[2*kk    ][0] - nm0, sf[2*kk    ][1] - nm0);
            pa[kk][1] = exp2_h2(sf[2*kk    ][2] - nm1, sf[2*kk    ][3] - nm1);
            pa[kk][2] = exp2_h2(sf[2*kk + 1][0] - nm0, sf[2*kk + 1][1] - nm0);
            pa[kk][3] = exp2_h2(sf[2*kk + 1][2] - nm1, sf[2*kk + 1][3] - nm1);
        }

        lacc[0] *= corr0; lacc[2] *= corr1;
#pragma unroll
        for (int nt = 0; nt < 4; nt++) {
            oacc[nt][0] *= corr0; oacc[nt][1] *= corr0;
            oacc[nt][2] *= corr1; oacc[nt][3] *= corr1;
        }

        // l: pre-sum P fragments across kk (fma pipe) + ONE ones-mma
        {
            uint32_t ps0 = hadd2u(hadd2u(pa[0][0], pa[1][0]), hadd2u(pa[2][0], pa[3][0]));
            uint32_t ps1 = hadd2u(hadd2u(pa[0][1], pa[1][1]), hadd2u(pa[2][1], pa[3][1]));
            uint32_t ps2 = hadd2u(hadd2u(pa[0][2], pa[1][2]), hadd2u(pa[2][2], pa[3][2]));
            uint32_t ps3 = hadd2u(hadd2u(pa[0][3], pa[1][3]), hadd2u(pa[2][3], pa[3][3]));
            mma_f16(lacc[0], lacc[1], lacc[2], lacc[3],
                    ps0, ps1, ps2, ps3, ONES_H2, ONES_H2);
        }

        // O += P @ V
#pragma unroll
        for (int kk = 0; kk < 4; kk++) {
#pragma unroll
            for (int np = 0; np < 2; np++) {     // nt pairs {0,1}, {2,3}
                uint32_t b0, b1, b2, b3;
                ldsm_x4_trans(b0, b1, b2, b3,
                    smem_u32(Vd + (kk * 16 + v_row) * 40 + np * 16 + v_col));
                mma_f16(oacc[2*np][0], oacc[2*np][1], oacc[2*np][2], oacc[2*np][3],
                        pa[kk][0], pa[kk][1], pa[kk][2], pa[kk][3], b0, b1);
                mma_f16(oacc[2*np+1][0], oacc[2*np+1][1], oacc[2*np+1][2], oacc[2*np+1][3],
                        pa[kk][0], pa[kk][1], pa[kk][2], pa[kk][3], b2, b3);
            }
        }

        s = (s == 2) ? 0 : s + 1;
        sl = (sl == 2) ? 0 : sl + 1;
    }

    float inv0 = 1.f / lacc[0], inv1 = 1.f / lacc[2];
    uint32_t* Ou = reinterpret_cast<uint32_t*>(
        O + (brow + q0) * DIMC + h * HEAD_DIM);
#pragma unroll
    for (int nt = 0; nt < 4; nt++) {
        Ou[(grp    ) * 128 + nt * 4 + tig] =
            h2u(oacc[nt][0] * inv0, oacc[nt][1] * inv0);
        Ou[(grp + 8) * 128 + nt * 4 + tig] =
            h2u(oacc[nt][2] * inv1, oacc[nt][3] * inv1);
    }
}

// ---------------------------------------------------------------------------
// Launch
// ---------------------------------------------------------------------------
extern "C" void kernel_launch(void* const* d_in, const int* in_sizes, int n_in,
                              void* d_out, int out_size)
{
    const float* x0      = (const float*)d_in[0];
    const float* x1      = (const float*)d_in[1];
    const float* qk_w    = (const float*)d_in[2];
    const float* v_w     = (const float*)d_in[3];
    const float* merge_w = (const float*)d_in[4];
    const float* ln1_w   = (const float*)d_in[5];
    const float* ln1_b   = (const float*)d_in[6];
    const float* ln2_w   = (const float*)d_in[7];
    const float* ln2_b   = (const float*)d_in[8];
    const float* fc1_w   = (const float*)d_in[9];
    const float* fc1_b   = (const float*)d_in[10];
    const float* fc2_w   = (const float*)d_in[11];
    const float* fc2_b   = (const float*)d_in[12];
    const float* gamma   = (const float*)d_in[13];
    float* out = (float*)d_out;

    __half *nbuf, *qk, *v, *m, *cat, *h;
    __half *wqk, *wv, *wm, *wf1, *wf2;
    float *t;
    cudaGetSymbolAddress((void**)&nbuf, g_n);
    cudaGetSymbolAddress((void**)&qk,   g_qk);
    cudaGetSymbolAddress((void**)&v,    g_v);
    cudaGetSymbolAddress((void**)&m,    g_m);
    cudaGetSymbolAddress((void**)&cat,  g_cat);
    cudaGetSymbolAddress((void**)&h,    g_h);
    cudaGetSymbolAddress((void**)&t,    g_t);
    cudaGetSymbolAddress((void**)&wqk,  g_wqk);
    cudaGetSymbolAddress((void**)&wv,   g_wv);
    cudaGetSymbolAddress((void**)&wm,   g_wm);
    cudaGetSymbolAddress((void**)&wf1,  g_wf1);
    cudaGetSymbolAddress((void**)&wf2,  g_wf2);

    cudaFuncSetAttribute(gemm_tc<false, false, true, true>,
                         cudaFuncAttributeMaxDynamicSharedMemorySize, GEMM_SMEM);
    cudaFuncSetAttribute(gemm_tc<false, false, false, true>,
                         cudaFuncAttributeMaxDynamicSharedMemorySize, GEMM_SMEM);
    cudaFuncSetAttribute(gemm_tc<true, true, false, true>,
                         cudaFuncAttributeMaxDynamicSharedMemorySize, GEMM_SMEM);
    cudaFuncSetAttribute(gemm_tc<false, true, false, false>,
                         cudaFuncAttributeMaxDynamicSharedMemorySize, GEMM_SMEM);
    cudaFuncSetAttribute(flash_tc,
                         cudaFuncAttributeMaxDynamicSharedMemorySize, FLASH_SMEM);

    // 1. Fused weight-cvt + LayerNorm1 (also writes h(x) into cat[:,0:256])
    ln_cvt_kernel<<<CVT_BLOCKS + LN_BLOCKS, 256>>>(
        x0, x1, ln1_w, ln1_b, qk_w, v_w, merge_w, fc1_w, fc2_w, nbuf, cat);

    // 2. Fused qk+v projection; qk carries HEAD_DIM^-.25 * sqrt(log2 e)
    dim3 gP2(2 * DIMC / 128, TOTAL_ROWS / 128);
    gemm_tc<false, false, true, true><<<gP2, 256, GEMM_SMEM>>>(
        nbuf, wqk, wv, nullptr, qk, v, DIMC, DIMC, DIMC, QK_SCALE_L2, 1.f);

    // 3. Flash attention, both directions
    dim3 gF(SEQ / 128, HEADS, 2 * BATCH);
    flash_tc<<<gF, 256, FLASH_SMEM>>>(qk, v, m);

    // 4. Merge projection -> cat[:,256:512] (ldC=512)
    dim3 gP(DIMC / 128, TOTAL_ROWS / 128);
    gemm_tc<false, false, false, true><<<gP, 256, GEMM_SMEM>>>(
        m, wm, nullptr, nullptr, cat + DIMC, nullptr,
        DIMC, DIMC, 2 * DIMC, 1.f, 1.f);

    // 5. fc1 + exact GELU (K=512 GEMM on cat)
    dim3 gF1(HIDDEN / 128, TOTAL_ROWS / 128);
    gemm_tc<true, true, false, true><<<gF1, 256, GEMM_SMEM>>>(
        cat, wf1, nullptr, fc1_b, h, nullptr,
        HIDDEN, 2 * DIMC, HIDDEN, 1.f, 1.f);

    // 6. fc2 (fp32 output for LN2)
    gemm_tc<false, true, false, false><<<gP, 256, GEMM_SMEM>>>(
        h, wf2, nullptr, fc2_b, t, nullptr,
        DIMC, HIDDEN, DIMC, 1.f, 1.f);

    // 7. Residual + gamma * LN2 (both streams)
    final_kernel<<<TOTAL_ROWS / 8, 256>>>(t, x0, x1, ln2_w, ln2_b, gamma, out);
}

// round 15
// speedup vs baseline: 1.0439x; 1.0439x over previous
#include <cuda_runtime.h>
#include <cuda_fp16.h>
#include <cstdint>

// ---------------------------------------------------------------------------
// Problem constants
// ---------------------------------------------------------------------------
#define DIMC      256
#define HEADS     8
#define HEAD_DIM  32
#define HIDDEN    1024
#define SEQ       2048
#define BATCH     2
#define RPS       (BATCH * SEQ)          // 4096 rows per stream
#define TOTAL_ROWS (2 * RPS)             // 8192
#define STREAM_OFF (RPS * DIMC)

// HEAD_DIM^-0.25 * sqrt(log2(e)) : scores come out in log2-units
#define QK_SCALE_L2 (0.42044820762685725f * 1.2011224087864498f)
#define ONES_H2 0x3C003C00u

// ---------------------------------------------------------------------------
// Scratch
// ---------------------------------------------------------------------------
__device__ __half g_n  [TOTAL_ROWS * DIMC];       // LN1 out
__device__ __half g_qk [TOTAL_ROWS * DIMC];       // log2-scaled
__device__ __half g_v  [TOTAL_ROWS * DIMC];
__device__ __half g_m  [TOTAL_ROWS * DIMC];       // flash out
__device__ __half g_cat[TOTAL_ROWS * 2 * DIMC];   // [h(x) | h(merge)]
__device__ __half g_h  [TOTAL_ROWS * HIDDEN];     // fc1 out
__device__ float  g_t  [TOTAL_ROWS * DIMC];       // fc2 partial 0 (with bias)
__device__ float  g_t2 [TOTAL_ROWS * DIMC];       // fc2 partial 1

__device__ __half g_wqk[DIMC * DIMC];
__device__ __half g_wv [DIMC * DIMC];
__device__ __half g_wm [DIMC * DIMC];
__device__ __half g_wf1[HIDDEN * 2 * DIMC];
__device__ __half g_wf2[DIMC * HIDDEN];

// ---------------------------------------------------------------------------
// PTX helpers
// ---------------------------------------------------------------------------
__device__ __forceinline__ void mma_f16(
    float& c0, float& c1, float& c2, float& c3,
    uint32_t a0, uint32_t a1, uint32_t a2, uint32_t a3,
    uint32_t b0, uint32_t b1)
{
    asm volatile(
        "mma.sync.aligned.m16n8k16.row.col.f32.f16.f16.f32 "
        "{%0,%1,%2,%3},{%4,%5,%6,%7},{%8,%9},{%0,%1,%2,%3};"
        : "+f"(c0), "+f"(c1), "+f"(c2), "+f"(c3)
        : "r"(a0), "r"(a1), "r"(a2), "r"(a3), "r"(b0), "r"(b1));
}

__device__ __forceinline__ uint32_t smem_u32(const void* p) {
    return (uint32_t)__cvta_generic_to_shared(p);
}
__device__ __forceinline__ void cp_async16(uint32_t dst, const void* src) {
    asm volatile("cp.async.cg.shared.global [%0], [%1], 16;"
                 :: "r"(dst), "l"(src));
}
__device__ __forceinline__ void cp_commit() {
    asm volatile("cp.async.commit_group;");
}
template <int N>
__device__ __forceinline__ void cp_wait() {
    asm volatile("cp.async.wait_group %0;" :: "n"(N));
}
__device__ __forceinline__ void ldsm_x4(uint32_t& r0, uint32_t& r1,
                                        uint32_t& r2, uint32_t& r3,
                                        uint32_t addr) {
    asm volatile("ldmatrix.sync.aligned.m8n8.x4.shared.b16 {%0,%1,%2,%3}, [%4];"
                 : "=r"(r0), "=r"(r1), "=r"(r2), "=r"(r3) : "r"(addr));
}
__device__ __forceinline__ void ldsm_x4_trans(uint32_t& r0, uint32_t& r1,
                                              uint32_t& r2, uint32_t& r3,
                                              uint32_t addr) {
    asm volatile("ldmatrix.sync.aligned.m8n8.x4.trans.shared.b16 {%0,%1,%2,%3}, [%4];"
                 : "=r"(r0), "=r"(r1), "=r"(r2), "=r"(r3) : "r"(addr));
}
__device__ __forceinline__ uint32_t h2u(float a, float b) {
    __half2 h = __floats2half2_rn(a, b);
    return *reinterpret_cast<uint32_t*>(&h);
}
__device__ __forceinline__ uint32_t hadd2u(uint32_t a, uint32_t b) {
    uint32_t r;
    asm("add.f16x2 %0, %1, %2;" : "=r"(r) : "r"(a), "r"(b));
    return r;
}
// pack (lo,hi) to f16x2 then exp2 both halves
__device__ __forceinline__ uint32_t exp2_h2(float lo, float hi) {
    uint32_t r;
    asm("{\n\t.reg .b32 t;\n\t"
        "cvt.rn.f16x2.f32 t, %2, %1;\n\t"
        "ex2.approx.f16x2 %0, t;\n\t}"
        : "=r"(r) : "f"(lo), "f"(hi));
    return r;
}
__device__ __forceinline__ float exp2_f32(float x) {
    float y;
    asm("ex2.approx.ftz.f32 %0, %1;" : "=f"(y) : "f"(x));
    return y;
}

// ---------------------------------------------------------------------------
// Fused: weight conversion fp32->fp16 (blocks 0..1919) + LayerNorm over both
// streams (blocks 1920..2943, one warp per row).
// ---------------------------------------------------------------------------
#define CVT_BLOCKS 1920
#define LN_BLOCKS  (TOTAL_ROWS / 8)

__global__ __launch_bounds__(256) void ln_cvt_kernel(
    const float* __restrict__ x0, const float* __restrict__ x1,
    const float* __restrict__ w, const float* __restrict__ b,
    const float* __restrict__ qk_w, const float* __restrict__ v_w,
    const float* __restrict__ mw,   const float* __restrict__ f1w,
    const float* __restrict__ f2w,
    __half* __restrict__ out, __half* __restrict__ cat)
{
    int bx = blockIdx.x;
    if (bx < CVT_BLOCKS) {
        int i = bx * 256 + threadIdx.x;
        const float2* s; __half2* d; int off;
        if      (i <  32768) { s = (const float2*)qk_w; d = (__half2*)g_wqk; off = i; }
        else if (i <  65536) { s = (const float2*)v_w;  d = (__half2*)g_wv;  off = i -  32768; }
        else if (i <  98304) { s = (const float2*)mw;   d = (__half2*)g_wm;  off = i -  65536; }
        else if (i < 360448) { s = (const float2*)f1w;  d = (__half2*)g_wf1; off = i -  98304; }
        else                 { s = (const float2*)f2w;  d = (__half2*)g_wf2; off = i - 360448; }
        float2 f = s[off];
        d[off] = __floats2half2_rn(f.x, f.y);
        return;
    }
    int warp = threadIdx.x >> 5, lane = threadIdx.x & 31;
    int row = (bx - CVT_BLOCKS) * 8 + warp;
    const float* xr = (row < RPS) ? x0 + (size_t)row * DIMC
                                  : x1 + (size_t)(row - RPS) * DIMC;
    float v[8];
    float sum = 0.f;
#pragma unroll
    for (int i = 0; i < 8; i++) { v[i] = xr[lane + i * 32]; sum += v[i]; }
#pragma unroll
    for (int o = 16; o; o >>= 1) sum += __shfl_xor_sync(0xffffffffu, sum, o);
    float mean = sum * (1.f / 256.f);
    float vs = 0.f;
#pragma unroll
    for (int i = 0; i < 8; i++) { float d = v[i] - mean; vs += d * d; }
#pragma unroll
    for (int o = 16; o; o >>= 1) vs += __shfl_xor_sync(0xffffffffu, vs, o);
    float rstd = rsqrtf(vs * (1.f / 256.f) + 1e-5f);
    __half* orow = out + (size_t)row * DIMC;
    __half* crow = cat + (size_t)row * (2 * DIMC);
#pragma unroll
    for (int i = 0; i < 8; i++) {
        int c = lane + i * 32;
        orow[c] = __float2half_rn((v[i] - mean) * rstd * w[c] + b[c]);
        crow[c] = __float2half_rn(v[i]);
    }
}

// ---------------------------------------------------------------------------
// Final: out = x + gamma * LayerNorm(t0 + t1)   (fc2 split-K reduction fused)
// ---------------------------------------------------------------------------
__global__ __launch_bounds__(256) void final_kernel(
    const float* __restrict__ t0p, const float* __restrict__ t1p,
    const float* __restrict__ x0, const float* __restrict__ x1,
    const float* __restrict__ w, const float* __restrict__ b,
    const float* __restrict__ gamma, float* __restrict__ out)
{
    int warp = threadIdx.x >> 5, lane = threadIdx.x & 31;
    int row = blockIdx.x * 8 + warp;
    const float* tr0 = t0p + (size_t)row * DIMC;
    const float* tr1 = t1p + (size_t)row * DIMC;
    const float* xr = (row < RPS) ? x0 + (size_t)row * DIMC
                                  : x1 + (size_t)(row - RPS) * DIMC;
    float v[8];
    float sum = 0.f;
#pragma unroll
    for (int i = 0; i < 8; i++) {
        int c = lane + i * 32;
        v[i] = tr0[c] + tr1[c];
        sum += v[i];
    }
#pragma unroll
    for (int o = 16; o; o >>= 1) sum += __shfl_xor_sync(0xffffffffu, sum, o);
    float mean = sum * (1.f / 256.f);
    float vs = 0.f;
#pragma unroll
    for (int i = 0; i < 8; i++) { float d = v[i] - mean; vs += d * d; }
#pragma unroll
    for (int o = 16; o; o >>= 1) vs += __shfl_xor_sync(0xffffffffu, vs, o);
    float rstd = rsqrtf(vs * (1.f / 256.f) + 1e-5f);
    float* orow = out + (size_t)row * DIMC;
#pragma unroll
    for (int i = 0; i < 8; i++) {
        int c = lane + i * 32;
        float ln = (v[i] - mean) * rstd * w[c] + b[c];
        orow[c] = xr[c] + gamma[c] * ln;
    }
}

// ---------------------------------------------------------------------------
// cp.async 3-stage fp16 GEMM, ldmatrix fragment loads.
// BM=128, BN=128, BK=32, 256 threads (8 warps 2x4), warp tile 64x32, m16n8k16.
// SPLITK: blockIdx.z selects K-half; z=0 -> C0 (+bias), z=1 -> C1 (no bias).
// ---------------------------------------------------------------------------
#define GEMM_SMEM (3 * (128 + 128) * 40 * 2)

template <bool GELU, bool HAS_BIAS, bool DUAL, bool HALF_OUT, bool SPLITK>
__global__ __launch_bounds__(256, 2) void gemm_tc(
    const __half* __restrict__ A0,
    const __half* __restrict__ B0, const __half* __restrict__ B1,
    const float* __restrict__ bias,
    void* __restrict__ C0, void* __restrict__ C1,
    int Nout, int K, int ldC, float alpha0, float alpha1)
{
    constexpr int BK = 32;
    extern __shared__ __half dsm[];
    __half* AsBase = dsm;                    // [3][128][40]
    __half* BsBase = dsm + 3 * 128 * 40;     // [3][128][40]

    int tid = threadIdx.x;
    int wid = tid >> 5, lane = tid & 31;
    int grp = lane >> 2, tig = lane & 3;
    int lm = lane >> 3, lr = lane & 7;
    int warp_m = wid >> 2, warp_n = wid & 3;
    int m0 = blockIdx.y * 128;
    int n0 = blockIdx.x * 128;

    int a_row = warp_m * 64 + (lm & 1) * 8 + lr;
    int a_col = (lm >> 1) * 8;
    int b_row = warp_n * 32 + (lm >> 1) * 8 + lr;
    int b_col = (lm & 1) * 8;

    const __half* Ap = A0;
    const __half* Bp;
    void* Cp;
    float alpha;
    if (DUAL) {
        if (n0 < Nout) { Bp = B0 + (size_t)n0 * K; Cp = C0; alpha = alpha0; }
        else { n0 -= Nout; Bp = B1 + (size_t)n0 * K; Cp = C1; alpha = alpha1; }
    } else {
        Bp = B0 + (size_t)n0 * K; Cp = C0; alpha = alpha0;
    }

    int Keff = K;
    bool add_bias = HAS_BIAS;
    if (SPLITK) {
        int half = K >> 1;
        Keff = half;
        if (blockIdx.z) {
            Ap += half; Bp += half; Cp = C1;
            add_bias = false;
        }
    }

    float acc[4][4][4] = {};
    int KT = Keff / BK;

    auto load_stage = [&](int ktb, int s) {
        __half* Ad = AsBase + s * (128 * 40);
        __half* Bd = BsBase + s * (128 * 40);
#pragma unroll
        for (int j = 0; j < 2; j++) {
            int idx = tid + j * 256;
            int r = idx >> 2, c = idx & 3;
            cp_async16(smem_u32(&Ad[r * 40 + c * 8]),
                       Ap + (size_t)(m0 + r) * K + ktb + c * 8);
        }
#pragma unroll
        for (int j = 0; j < 2; j++) {
            int idx = tid + j * 256;
            int r = idx >> 2, c = idx & 3;
            cp_async16(smem_u32(&Bd[r * 40 + c * 8]),
                       Bp + (size_t)r * K + ktb + c * 8);
        }
        cp_commit();
    };

    load_stage(0, 0);
    if (KT > 1) load_stage(BK, 1);
    else        cp_commit();

    int s = 0, sl = 2;
    for (int kt = 0; kt < KT; kt++) {
        if (kt + 2 < KT) {
            load_stage((kt + 2) * BK, sl);
            cp_wait<2>();
        } else if (kt + 1 < KT) {
            cp_wait<1>();
        } else {
            cp_wait<0>();
        }
        __syncthreads();

        const __half* Ad = AsBase + s * (128 * 40);
        const __half* Bd = BsBase + s * (128 * 40);
#pragma unroll
        for (int kc = 0; kc < 2; kc++) {
            uint32_t af[4][4], bf[4][2];
#pragma unroll
            for (int mt = 0; mt < 4; mt++)
                ldsm_x4(af[mt][0], af[mt][1], af[mt][2], af[mt][3],
                        smem_u32(Ad + (a_row + mt * 16) * 40 + a_col + kc * 16));
#pragma unroll
            for (int p = 0; p < 2; p++) {
                uint32_t r0, r1, r2, r3;
                ldsm_x4(r0, r1, r2, r3,
                        smem_u32(Bd + (b_row + p * 16) * 40 + b_col + kc * 16));
                bf[2 * p][0] = r0; bf[2 * p][1] = r1;
                bf[2 * p + 1][0] = r2; bf[2 * p + 1][1] = r3;
            }
#pragma unroll
            for (int mt = 0; mt < 4; mt++)
#pragma unroll
                for (int nt = 0; nt < 4; nt++)
                    mma_f16(acc[mt][nt][0], acc[mt][nt][1],
                            acc[mt][nt][2], acc[mt][nt][3],
                            af[mt][0], af[mt][1], af[mt][2], af[mt][3],
                            bf[nt][0], bf[nt][1]);
        }
        __syncthreads();
        s = (s == 2) ? 0 : s + 1;
        sl = (sl == 2) ? 0 : sl + 1;
    }

#pragma unroll
    for (int mt = 0; mt < 4; mt++) {
        int mr = m0 + warp_m * 64 + mt * 16;
#pragma unroll
        for (int nt = 0; nt < 4; nt++) {
            int nc = n0 + warp_n * 32 + nt * 8 + 2 * tig;
            float b0 = 0.f, b1 = 0.f;
            if (HAS_BIAS && add_bias) { b0 = bias[nc]; b1 = bias[nc + 1]; }
            float v0 = acc[mt][nt][0] * alpha + b0;
            float v1 = acc[mt][nt][1] * alpha + b1;
            float v2 = acc[mt][nt][2] * alpha + b0;
            float v3 = acc[mt][nt][3] * alpha + b1;
            if (GELU) {
                v0 = 0.5f * v0 * (1.f + erff(v0 * 0.70710678118654752f));
                v1 = 0.5f * v1 * (1.f + erff(v1 * 0.70710678118654752f));
                v2 = 0.5f * v2 * (1.f + erff(v2 * 0.70710678118654752f));
                v3 = 0.5f * v3 * (1.f + erff(v3 * 0.70710678118654752f));
            }
            if (HALF_OUT) {
                uint32_t* Ch = (uint32_t*)Cp;
                Ch[((size_t)(mr + grp    ) * ldC + nc) >> 1] = h2u(v0, v1);
                Ch[((size_t)(mr + grp + 8) * ldC + nc) >> 1] = h2u(v2, v3);
            } else {
                float* Cf = (float*)Cp;
                *reinterpret_cast<float2*>(&Cf[(size_t)(mr + grp) * ldC + nc]) =
                    make_float2(v0, v1);
                *reinterpret_cast<float2*>(&Cf[(size_t)(mr + grp + 8) * ldC + nc]) =
                    make_float2(v2, v3);
            }
        }
    }
}

// ---------------------------------------------------------------------------
// fp16 flash attention: 128-thread CTAs (4 warps, 64 queries) for natural
// cross-CTA desync of the softmax phase; 16 queries/warp, register-resident P,
// exp2 softmax, l via pre-summed P + single ones-mma, V via ldmatrix.x4.trans,
// 3-stage cp.async K/V pipeline, one __syncthreads per chunk.
// grid: (SEQ/64, HEADS, 2*BATCH) = 1024 CTAs.
// smem: K [3][64][40]h + V [3][64][40]h = 30720 B.
// ---------------------------------------------------------------------------
#define FLASH_SMEM ((3*64*40 + 3*64*40) * 2)

__global__ __launch_bounds__(128, 5) void flash_tc(
    const __half* __restrict__ qkb, const __half* __restrict__ vb,
    __half* __restrict__ mb)
{
    extern __shared__ __half dsm[];
    __half* KsB = dsm;                       // [3][64][40]
    __half* VsB = dsm + 3 * 64 * 40;         // [3][64][40]

    int tid = threadIdx.x;
    int wid = tid >> 5, lane = tid & 31;
    int grp = lane >> 2, tig = lane & 3;
    int lm = lane >> 3, lr = lane & 7;
    int h = blockIdx.y;
    int z = blockIdx.z;
    int b = z & 1, dir = z >> 1;

    const __half* Q  = dir ? qkb + STREAM_OFF : qkb;
    const __half* Kp = dir ? qkb : qkb + STREAM_OFF;
    const __half* Vp = dir ? vb  : vb  + STREAM_OFF;
    __half*       O  = dir ? mb + STREAM_OFF : mb;

    size_t brow = (size_t)b * SEQ;
    int q0 = blockIdx.x * 64 + wid * 16;

    // ldmatrix lane addressing
    int k_row = (lm >> 1) * 8 + lr;          // K: + p*16 ; col (lm&1)*8 + kk*16
    int k_col = (lm & 1) * 8;
    int v_row = (lm & 1) * 8 + lr;           // V trans: + kk*16 ; col (lm>>1)*8
    int v_col = (lm >> 1) * 8;

    // register-resident Q fragments: 2 k16-chunks over dh=32
    uint32_t qa[2][4];
    const uint32_t* Qu = reinterpret_cast<const uint32_t*>(
        Q + (brow + q0) * DIMC + h * HEAD_DIM);
#pragma unroll
    for (int kc = 0; kc < 2; kc++) {
        qa[kc][0] = Qu[(grp    ) * 128 + kc * 8 + tig    ];
        qa[kc][1] = Qu[(grp + 8) * 128 + kc * 8 + tig    ];
        qa[kc][2] = Qu[(grp    ) * 128 + kc * 8 + tig + 4];
        qa[kc][3] = Qu[(grp + 8) * 128 + kc * 8 + tig + 4];
    }

    auto load_chunk = [&](int kc, int s) {
        __half* Kd = KsB + s * (64 * 40);
        __half* Vd = VsB + s * (64 * 40);
#pragma unroll
        for (int j = 0; j < 2; j++) {        // 64 rows x 4 16B-chunks, 128 thr
            int idx = tid + j * 128;
            int r = idx >> 2, c = idx & 3;
            size_t g = (brow + (size_t)kc * 64 + r) * DIMC + h * HEAD_DIM + c * 8;
            cp_async16(smem_u32(&Kd[r * 40 + c * 8]), Kp + g);
            cp_async16(smem_u32(&Vd[r * 40 + c * 8]), Vp + g);
        }
        cp_commit();
    };

    float oacc[4][4] = {};
    float lacc[4] = {};
    float mr0 = -1e30f, mr1 = -1e30f;
    constexpr int NC = SEQ / 64;

    load_chunk(0, 0);
    load_chunk(1, 1);

    int s = 0, sl = 2;
    for (int kc = 0; kc < NC; kc++) {
        if (kc + 1 < NC) cp_wait<1>();
        else             cp_wait<0>();
        __syncthreads();
        if (kc + 2 < NC) load_chunk(kc + 2, sl);

        const __half* Kd = KsB + s * (64 * 40);
        const __half* Vd = VsB + s * (64 * 40);

        // S = Q @ K^T : scores in log2 units (scale baked into qk)
        float sf[8][4] = {};
#pragma unroll
        for (int kk = 0; kk < 2; kk++) {
            uint32_t bf[8][2];
#pragma unroll
            for (int p = 0; p < 4; p++) {
                uint32_t r0, r1, r2, r3;
                ldsm_x4(r0, r1, r2, r3,
                        smem_u32(Kd + (k_row + p * 16) * 40 + k_col + kk * 16));
                bf[2 * p][0] = r0; bf[2 * p][1] = r1;
                bf[2 * p + 1][0] = r2; bf[2 * p + 1][1] = r3;
            }
#pragma unroll
            for (int nt = 0; nt < 8; nt++)
                mma_f16(sf[nt][0], sf[nt][1], sf[nt][2], sf[nt][3],
                        qa[kk][0], qa[kk][1], qa[kk][2], qa[kk][3],
                        bf[nt][0], bf[nt][1]);
        }

        // online softmax (log2 domain)
        float cm0 = -1e30f, cm1 = -1e30f;
#pragma unroll
        for (int nt = 0; nt < 8; nt++) {
            cm0 = fmaxf(cm0, fmaxf(sf[nt][0], sf[nt][1]));
            cm1 = fmaxf(cm1, fmaxf(sf[nt][2], sf[nt][3]));
        }
        cm0 = fmaxf(cm0, __shfl_xor_sync(0xffffffffu, cm0, 1));
        cm0 = fmaxf(cm0, __shfl_xor_sync(0xffffffffu, cm0, 2));
        cm1 = fmaxf(cm1, __shfl_xor_sync(0xffffffffu, cm1, 1));
        cm1 = fmaxf(cm1, __shfl_xor_sync(0xffffffffu, cm1, 2));
        float nm0 = fmaxf(mr0, cm0), nm1 = fmaxf(mr1, cm1);
        float corr0 = exp2_f32(mr0 - nm0), corr1 = exp2_f32(mr1 - nm1);
        mr0 = nm0; mr1 = nm1;

        // P = exp2(s - m) straight into PV A-fragments
        uint32_t pa[4][4];
#pragma unroll
        for (int kk = 0; kk < 4; kk++) {
            pa[kk][0] = exp2_h2(sf[2*kk    ][0] - nm0, sf[2*kk    ][1] - nm0);
            pa[kk][1] = exp2_h2(sf[2*kk    ][2] - nm1, sf[2*kk    ][3] - nm1);
            pa[kk][2] = exp2_h2(sf[2*kk + 1][0] - nm0, sf[2*kk + 1][1] - nm0);
            pa[kk][3] = exp2_h2(sf[2*kk + 1][2] - nm1, sf[2*kk + 1][3] - nm1);
        }

        lacc[0] *= corr0; lacc[2] *= corr1;
#pragma unroll
        for (int nt = 0; nt < 4; nt++) {
            oacc[nt][0] *= corr0; oacc[nt][1] *= corr0;
            oacc[nt][2] *= corr1; oacc[nt][3] *= corr1;
        }

        // l: pre-sum P fragments across kk + single ones-mma
        {
            uint32_t ps0 = hadd2u(hadd2u(pa[0][0], pa[1][0]), hadd2u(pa[2][0], pa[3][0]));
            uint32_t ps1 = hadd2u(hadd2u(pa[0][1], pa[1][1]), hadd2u(pa[2][1], pa[3][1]));
            uint32_t ps2 = hadd2u(hadd2u(pa[0][2], pa[1][2]), hadd2u(pa[2][2], pa[3][2]));
            uint32_t ps3 = hadd2u(hadd2u(pa[0][3], pa[1][3]), hadd2u(pa[2][3], pa[3][3]));
            mma_f16(lacc[0], lacc[1], lacc[2], lacc[3],
                    ps0, ps1, ps2, ps3, ONES_H2, ONES_H2);
        }

        // O += P @ V
#pragma unroll
        for (int kk = 0; kk < 4; kk++) {
#pragma unroll
            for (int np = 0; np < 2; np++) {
                uint32_t b0, b1, b2, b3;
                ldsm_x4_trans(b0, b1, b2, b3,
                    smem_u32(Vd + (kk * 16 + v_row) * 40 + np * 16 + v_col));
                mma_f16(oacc[2*np][0], oacc[2*np][1], oacc[2*np][2], oacc[2*np][3],
                        pa[kk][0], pa[kk][1], pa[kk][2], pa[kk][3], b0, b1);
                mma_f16(oacc[2*np+1][0], oacc[2*np+1][1], oacc[2*np+1][2], oacc[2*np+1][3],
                        pa[kk][0], pa[kk][1], pa[kk][2], pa[kk][3], b2, b3);
            }
        }

        s = (s == 2) ? 0 : s + 1;
        sl = (sl == 2) ? 0 : sl + 1;
    }

    float inv0 = 1.f / lacc[0], inv1 = 1.f / lacc[2];
    uint32_t* Ou = reinterpret_cast<uint32_t*>(
        O + (brow + q0) * DIMC + h * HEAD_DIM);
#pragma unroll
    for (int nt = 0; nt < 4; nt++) {
        Ou[(grp    ) * 128 + nt * 4 + tig] =
            h2u(oacc[nt][0] * inv0, oacc[nt][1] * inv0);
        Ou[(grp + 8) * 128 + nt * 4 + tig] =
            h2u(oacc[nt][2] * inv1, oacc[nt][3] * inv1);
    }
}

// ---------------------------------------------------------------------------
// Launch
// ---------------------------------------------------------------------------
extern "C" void kernel_launch(void* const* d_in, const int* in_sizes, int n_in,
                              void* d_out, int out_size)
{
    const float* x0      = (const float*)d_in[0];
    const float* x1      = (const float*)d_in[1];
    const float* qk_w    = (const float*)d_in[2];
    const float* v_w     = (const float*)d_in[3];
    const float* merge_w = (const float*)d_in[4];
    const float* ln1_w   = (const float*)d_in[5];
    const float* ln1_b   = (const float*)d_in[6];
    const float* ln2_w   = (const float*)d_in[7];
    const float* ln2_b   = (const float*)d_in[8];
    const float* fc1_w   = (const float*)d_in[9];
    const float* fc1_b   = (const float*)d_in[10];
    const float* fc2_w   = (const float*)d_in[11];
    const float* fc2_b   = (const float*)d_in[12];
    const float* gamma   = (const float*)d_in[13];
    float* out = (float*)d_out;

    __half *nbuf, *qk, *v, *m, *cat, *h;
    __half *wqk, *wv, *wm, *wf1, *wf2;
    float *t, *t2;
    cudaGetSymbolAddress((void**)&nbuf, g_n);
    cudaGetSymbolAddress((void**)&qk,   g_qk);
    cudaGetSymbolAddress((void**)&v,    g_v);
    cudaGetSymbolAddress((void**)&m,    g_m);
    cudaGetSymbolAddress((void**)&cat,  g_cat);
    cudaGetSymbolAddress((void**)&h,    g_h);
    cudaGetSymbolAddress((void**)&t,    g_t);
    cudaGetSymbolAddress((void**)&t2,   g_t2);
    cudaGetSymbolAddress((void**)&wqk,  g_wqk);
    cudaGetSymbolAddress((void**)&wv,   g_wv);
    cudaGetSymbolAddress((void**)&wm,   g_wm);
    cudaGetSymbolAddress((void**)&wf1,  g_wf1);
    cudaGetSymbolAddress((void**)&wf2,  g_wf2);

    cudaFuncSetAttribute(gemm_tc<false, false, true, true, false>,
                         cudaFuncAttributeMaxDynamicSharedMemorySize, GEMM_SMEM);
    cudaFuncSetAttribute(gemm_tc<false, false, false, true, false>,
                         cudaFuncAttributeMaxDynamicSharedMemorySize, GEMM_SMEM);
    cudaFuncSetAttribute(gemm_tc<true, true, false, true, false>,
                         cudaFuncAttributeMaxDynamicSharedMemorySize, GEMM_SMEM);
    cudaFuncSetAttribute(gemm_tc<false, true, false, false, true>,
                         cudaFuncAttributeMaxDynamicSharedMemorySize, GEMM_SMEM);
    cudaFuncSetAttribute(flash_tc,
                         cudaFuncAttributeMaxDynamicSharedMemorySize, FLASH_SMEM);

    // 1. Fused weight-cvt + LayerNorm1 (also writes h(x) into cat[:,0:256])
    ln_cvt_kernel<<<CVT_BLOCKS + LN_BLOCKS, 256>>>(
        x0, x1, ln1_w, ln1_b, qk_w, v_w, merge_w, fc1_w, fc2_w, nbuf, cat);

    // 2. Fused qk+v projection; qk carries HEAD_DIM^-.25 * sqrt(log2 e)
    dim3 gP2(2 * DIMC / 128, TOTAL_ROWS / 128);
    gemm_tc<false, false, true, true, false><<<gP2, 256, GEMM_SMEM>>>(
        nbuf, wqk, wv, nullptr, qk, v, DIMC, DIMC, DIMC, QK_SCALE_L2, 1.f);

    // 3. Flash attention (128-thread CTAs, 1024 CTAs for desync)
    dim3 gF(SEQ / 64, HEADS, 2 * BATCH);
    flash_tc<<<gF, 128, FLASH_SMEM>>>(qk, v, m);

    // 4. Merge projection -> cat[:,256:512] (ldC=512)
    dim3 gP(DIMC / 128, TOTAL_ROWS / 128);
    gemm_tc<false, false, false, true, false><<<gP, 256, GEMM_SMEM>>>(
        m, wm, nullptr, nullptr, cat + DIMC, nullptr,
        DIMC, DIMC, 2 * DIMC, 1.f, 1.f);

    // 5. fc1 + exact GELU (K=512 GEMM on cat)
    dim3 gF1(HIDDEN / 128, TOTAL_ROWS / 128);
    gemm_tc<true, true, false, true, false><<<gF1, 256, GEMM_SMEM>>>(
        cat, wf1, nullptr, fc1_b, h, nullptr,
        HIDDEN, 2 * DIMC, HIDDEN, 1.f, 1.f);

    // 6. fc2 split-K=2 (z=0 -> t with bias, z=1 -> t2), 256 CTAs
    dim3 gP3(DIMC / 128, TOTAL_ROWS / 128, 2);
    gemm_tc<false, true, false, false, true><<<gP3, 256, GEMM_SMEM>>>(
        h, wf2, nullptr, fc2_b, t, t2,
        DIMC, HIDDEN, DIMC, 1.f, 1.f);

    // 7. Residual + gamma * LN2(t + t2)
    final_kernel<<<TOTAL_ROWS / 8, 256>>>(t, t2, x0, x1, ln2_w, ln2_b, gamma, out);
}

// round 16
// speedup vs baseline: 1.0512x; 1.0070x over previous
#include <cuda_runtime.h>
#include <cuda_fp16.h>
#include <cstdint>

// ---------------------------------------------------------------------------
// Problem constants
// ---------------------------------------------------------------------------
#define DIMC      256
#define HEADS     8
#define HEAD_DIM  32
#define HIDDEN    1024
#define SEQ       2048
#define BATCH     2
#define RPS       (BATCH * SEQ)          // 4096 rows per stream
#define TOTAL_ROWS (2 * RPS)             // 8192
#define STREAM_OFF (RPS * DIMC)

// HEAD_DIM^-0.25 * sqrt(log2(e)) : scores come out in log2-units
#define QK_SCALE_L2 (0.42044820762685725f * 1.2011224087864498f)
#define ONES_H2 0x3C003C00u

// ---------------------------------------------------------------------------
// Scratch
// ---------------------------------------------------------------------------
__device__ __half g_n  [TOTAL_ROWS * DIMC];       // LN1 out
__device__ __half g_qk [TOTAL_ROWS * DIMC];       // log2-scaled
__device__ __half g_v  [TOTAL_ROWS * DIMC];
__device__ __half g_m  [TOTAL_ROWS * DIMC];       // flash out
__device__ __half g_cat[TOTAL_ROWS * 2 * DIMC];   // [h(x) | h(merge)]
__device__ __half g_h  [TOTAL_ROWS * HIDDEN];     // fc1 out
__device__ float  g_t  [TOTAL_ROWS * DIMC];       // fc2 partial 0 (with bias)
__device__ float  g_t2 [TOTAL_ROWS * DIMC];       // fc2 partial 1

__device__ __half g_wqk[DIMC * DIMC];
__device__ __half g_wv [DIMC * DIMC];
__device__ __half g_wm [DIMC * DIMC];
__device__ __half g_wf1[HIDDEN * 2 * DIMC];
__device__ __half g_wf2[DIMC * HIDDEN];

// ---------------------------------------------------------------------------
// PTX helpers
// ---------------------------------------------------------------------------
__device__ __forceinline__ void mma_f16(
    float& c0, float& c1, float& c2, float& c3,
    uint32_t a0, uint32_t a1, uint32_t a2, uint32_t a3,
    uint32_t b0, uint32_t b1)
{
    asm volatile(
        "mma.sync.aligned.m16n8k16.row.col.f32.f16.f16.f32 "
        "{%0,%1,%2,%3},{%4,%5,%6,%7},{%8,%9},{%0,%1,%2,%3};"
        : "+f"(c0), "+f"(c1), "+f"(c2), "+f"(c3)
        : "r"(a0), "r"(a1), "r"(a2), "r"(a3), "r"(b0), "r"(b1));
}

__device__ __forceinline__ uint32_t smem_u32(const void* p) {
    return (uint32_t)__cvta_generic_to_shared(p);
}
__device__ __forceinline__ void cp_async16(uint32_t dst, const void* src) {
    asm volatile("cp.async.cg.shared.global [%0], [%1], 16;"
                 :: "r"(dst), "l"(src));
}
__device__ __forceinline__ void cp_commit() {
    asm volatile("cp.async.commit_group;");
}
template <int N>
__device__ __forceinline__ void cp_wait() {
    asm volatile("cp.async.wait_group %0;" :: "n"(N));
}
__device__ __forceinline__ void ldsm_x4(uint32_t& r0, uint32_t& r1,
                                        uint32_t& r2, uint32_t& r3,
                                        uint32_t addr) {
    asm volatile("ldmatrix.sync.aligned.m8n8.x4.shared.b16 {%0,%1,%2,%3}, [%4];"
                 : "=r"(r0), "=r"(r1), "=r"(r2), "=r"(r3) : "r"(addr));
}
__device__ __forceinline__ void ldsm_x4_trans(uint32_t& r0, uint32_t& r1,
                                              uint32_t& r2, uint32_t& r3,
                                              uint32_t addr) {
    asm volatile("ldmatrix.sync.aligned.m8n8.x4.trans.shared.b16 {%0,%1,%2,%3}, [%4];"
                 : "=r"(r0), "=r"(r1), "=r"(r2), "=r"(r3) : "r"(addr));
}
__device__ __forceinline__ uint32_t h2u(float a, float b) {
    __half2 h = __floats2half2_rn(a, b);
    return *reinterpret_cast<uint32_t*>(&h);
}
__device__ __forceinline__ uint32_t hadd2u(uint32_t a, uint32_t b) {
    uint32_t r;
    asm("add.f16x2 %0, %1, %2;" : "=r"(r) : "r"(a), "r"(b));
    return r;
}
// pack (lo,hi) to f16x2 then exp2 both halves
__device__ __forceinline__ uint32_t exp2_h2(float lo, float hi) {
    uint32_t r;
    asm("{\n\t.reg .b32 t;\n\t"
        "cvt.rn.f16x2.f32 t, %2, %1;\n\t"
        "ex2.approx.f16x2 %0, t;\n\t}"
        : "=r"(r) : "f"(lo), "f"(hi));
    return r;
}
__device__ __forceinline__ float exp2_f32(float x) {
    float y;
    asm("ex2.approx.ftz.f32 %0, %1;" : "=f"(y) : "f"(x));
    return y;
}

// ---------------------------------------------------------------------------
// Fused: weight conversion fp32->fp16 (blocks 0..1919) + LayerNorm over both
// streams (blocks 1920..2943, one warp per row).
// ---------------------------------------------------------------------------
#define CVT_BLOCKS 1920
#define LN_BLOCKS  (TOTAL_ROWS / 8)

__global__ __launch_bounds__(256) void ln_cvt_kernel(
    const float* __restrict__ x0, const float* __restrict__ x1,
    const float* __restrict__ w, const float* __restrict__ b,
    const float* __restrict__ qk_w, const float* __restrict__ v_w,
    const float* __restrict__ mw,   const float* __restrict__ f1w,
    const float* __restrict__ f2w,
    __half* __restrict__ out, __half* __restrict__ cat)
{
    int bx = blockIdx.x;
    if (bx < CVT_BLOCKS) {
        int i = bx * 256 + threadIdx.x;
        const float2* s; __half2* d; int off;
        if      (i <  32768) { s = (const float2*)qk_w; d = (__half2*)g_wqk; off = i; }
        else if (i <  65536) { s = (const float2*)v_w;  d = (__half2*)g_wv;  off = i -  32768; }
        else if (i <  98304) { s = (const float2*)mw;   d = (__half2*)g_wm;  off = i -  65536; }
        else if (i < 360448) { s = (const float2*)f1w;  d = (__half2*)g_wf1; off = i -  98304; }
        else                 { s = (const float2*)f2w;  d = (__half2*)g_wf2; off = i - 360448; }
        float2 f = s[off];
        d[off] = __floats2half2_rn(f.x, f.y);
        return;
    }
    int warp = threadIdx.x >> 5, lane = threadIdx.x & 31;
    int row = (bx - CVT_BLOCKS) * 8 + warp;
    const float* xr = (row < RPS) ? x0 + (size_t)row * DIMC
                                  : x1 + (size_t)(row - RPS) * DIMC;
    float v[8];
    float sum = 0.f;
#pragma unroll
    for (int i = 0; i < 8; i++) { v[i] = xr[lane + i * 32]; sum += v[i]; }
#pragma unroll
    for (int o = 16; o; o >>= 1) sum += __shfl_xor_sync(0xffffffffu, sum, o);
    float mean = sum * (1.f / 256.f);
    float vs = 0.f;
#pragma unroll
    for (int i = 0; i < 8; i++) { float d = v[i] - mean; vs += d * d; }
#pragma unroll
    for (int o = 16; o; o >>= 1) vs += __shfl_xor_sync(0xffffffffu, vs, o);
    float rstd = rsqrtf(vs * (1.f / 256.f) + 1e-5f);
    __half* orow = out + (size_t)row * DIMC;
    __half* crow = cat + (size_t)row * (2 * DIMC);
#pragma unroll
    for (int i = 0; i < 8; i++) {
        int c = lane + i * 32;
        orow[c] = __float2half_rn((v[i] - mean) * rstd * w[c] + b[c]);
        crow[c] = __float2half_rn(v[i]);
    }
}

// ---------------------------------------------------------------------------
// Final: out = x + gamma * LayerNorm(t0 + t1)   (fc2 split-K reduction fused)
// ---------------------------------------------------------------------------
__global__ __launch_bounds__(256) void final_kernel(
    const float* __restrict__ t0p, const float* __restrict__ t1p,
    const float* __restrict__ x0, const float* __restrict__ x1,
    const float* __restrict__ w, const float* __restrict__ b,
    const float* __restrict__ gamma, float* __restrict__ out)
{
    int warp = threadIdx.x >> 5, lane = threadIdx.x & 31;
    int row = blockIdx.x * 8 + warp;
    const float* tr0 = t0p + (size_t)row * DIMC;
    const float* tr1 = t1p + (size_t)row * DIMC;
    const float* xr = (row < RPS) ? x0 + (size_t)row * DIMC
                                  : x1 + (size_t)(row - RPS) * DIMC;
    float v[8];
    float sum = 0.f;
#pragma unroll
    for (int i = 0; i < 8; i++) {
        int c = lane + i * 32;
        v[i] = tr0[c] + tr1[c];
        sum += v[i];
    }
#pragma unroll
    for (int o = 16; o; o >>= 1) sum += __shfl_xor_sync(0xffffffffu, sum, o);
    float mean = sum * (1.f / 256.f);
    float vs = 0.f;
#pragma unroll
    for (int i = 0; i < 8; i++) { float d = v[i] - mean; vs += d * d; }
#pragma unroll
    for (int o = 16; o; o >>= 1) vs += __shfl_xor_sync(0xffffffffu, vs, o);
    float rstd = rsqrtf(vs * (1.f / 256.f) + 1e-5f);
    float* orow = out + (size_t)row * DIMC;
#pragma unroll
    for (int i = 0; i < 8; i++) {
        int c = lane + i * 32;
        float ln = (v[i] - mean) * rstd * w[c] + b[c];
        orow[c] = xr[c] + gamma[c] * ln;
    }
}

// ---------------------------------------------------------------------------
// cp.async 4-stage fp16 GEMM, ldmatrix fragment loads.
// BM=128, BN=128, BK=32, 256 threads (8 warps 2x4), warp tile 64x32, m16n8k16.
// SPLITK: blockIdx.z selects K-half; z=0 -> C0 (+bias), z=1 -> C1 (no bias).
// smem: 4 x (128+128) x 40 halves = 81920 B (2 CTAs/SM).
// Requires KT >= 3 (all GEMMs here have KT >= 8).
// ---------------------------------------------------------------------------
#define GEMM_SMEM (4 * (128 + 128) * 40 * 2)

template <bool GELU, bool HAS_BIAS, bool DUAL, bool HALF_OUT, bool SPLITK>
__global__ __launch_bounds__(256, 2) void gemm_tc(
    const __half* __restrict__ A0,
    const __half* __restrict__ B0, const __half* __restrict__ B1,
    const float* __restrict__ bias,
    void* __restrict__ C0, void* __restrict__ C1,
    int Nout, int K, int ldC, float alpha0, float alpha1)
{
    constexpr int BK = 32;
    extern __shared__ __half dsm[];
    __half* AsBase = dsm;                    // [4][128][40]
    __half* BsBase = dsm + 4 * 128 * 40;     // [4][128][40]

    int tid = threadIdx.x;
    int wid = tid >> 5, lane = tid & 31;
    int grp = lane >> 2, tig = lane & 3;
    int lm = lane >> 3, lr = lane & 7;
    int warp_m = wid >> 2, warp_n = wid & 3;
    int m0 = blockIdx.y * 128;
    int n0 = blockIdx.x * 128;

    int a_row = warp_m * 64 + (lm & 1) * 8 + lr;
    int a_col = (lm >> 1) * 8;
    int b_row = warp_n * 32 + (lm >> 1) * 8 + lr;
    int b_col = (lm & 1) * 8;

    const __half* Ap = A0;
    const __half* Bp;
    void* Cp;
    float alpha;
    if (DUAL) {
        if (n0 < Nout) { Bp = B0 + (size_t)n0 * K; Cp = C0; alpha = alpha0; }
        else { n0 -= Nout; Bp = B1 + (size_t)n0 * K; Cp = C1; alpha = alpha1; }
    } else {
        Bp = B0 + (size_t)n0 * K; Cp = C0; alpha = alpha0;
    }

    int Keff = K;
    bool add_bias = HAS_BIAS;
    if (SPLITK) {
        int half = K >> 1;
        Keff = half;
        if (blockIdx.z) {
            Ap += half; Bp += half; Cp = C1;
            add_bias = false;
        }
    }

    float acc[4][4][4] = {};
    int KT = Keff / BK;

    auto load_stage = [&](int ktb, int s) {
        __half* Ad = AsBase + s * (128 * 40);
        __half* Bd = BsBase + s * (128 * 40);
#pragma unroll
        for (int j = 0; j < 2; j++) {
            int idx = tid + j * 256;
            int r = idx >> 2, c = idx & 3;
            cp_async16(smem_u32(&Ad[r * 40 + c * 8]),
                       Ap + (size_t)(m0 + r) * K + ktb + c * 8);
        }
#pragma unroll
        for (int j = 0; j < 2; j++) {
            int idx = tid + j * 256;
            int r = idx >> 2, c = idx & 3;
            cp_async16(smem_u32(&Bd[r * 40 + c * 8]),
                       Bp + (size_t)r * K + ktb + c * 8);
        }
        cp_commit();
    };

    // prologue: fill 3 of 4 stages (KT >= 3 guaranteed)
    load_stage(0, 0);
    load_stage(BK, 1);
    load_stage(2 * BK, 2);

    for (int kt = 0; kt < KT; kt++) {
        if (kt + 3 < KT) {
            load_stage((kt + 3) * BK, (kt + 3) & 3);
            cp_wait<3>();
        } else if (kt + 2 < KT) {
            cp_wait<2>();
        } else if (kt + 1 < KT) {
            cp_wait<1>();
        } else {
            cp_wait<0>();
        }
        __syncthreads();

        int s = kt & 3;
        const __half* Ad = AsBase + s * (128 * 40);
        const __half* Bd = BsBase + s * (128 * 40);
#pragma unroll
        for (int kc = 0; kc < 2; kc++) {
            uint32_t af[4][4], bf[4][2];
#pragma unroll
            for (int mt = 0; mt < 4; mt++)
                ldsm_x4(af[mt][0], af[mt][1], af[mt][2], af[mt][3],
                        smem_u32(Ad + (a_row + mt * 16) * 40 + a_col + kc * 16));
#pragma unroll
            for (int p = 0; p < 2; p++) {
                uint32_t r0, r1, r2, r3;
                ldsm_x4(r0, r1, r2, r3,
                        smem_u32(Bd + (b_row + p * 16) * 40 + b_col + kc * 16));
                bf[2 * p][0] = r0; bf[2 * p][1] = r1;
                bf[2 * p + 1][0] = r2; bf[2 * p + 1][1] = r3;
            }
#pragma unroll
            for (int mt = 0; mt < 4; mt++)
#pragma unroll
                for (int nt = 0; nt < 4; nt++)
                    mma_f16(acc[mt][nt][0], acc[mt][nt][1],
                            acc[mt][nt][2], acc[mt][nt][3],
                            af[mt][0], af[mt][1], af[mt][2], af[mt][3],
                            bf[nt][0], bf[nt][1]);
        }
        __syncthreads();
    }

#pragma unroll
    for (int mt = 0; mt < 4; mt++) {
        int mr = m0 + warp_m * 64 + mt * 16;
#pragma unroll
        for (int nt = 0; nt < 4; nt++) {
            int nc = n0 + warp_n * 32 + nt * 8 + 2 * tig;
            float b0 = 0.f, b1 = 0.f;
            if (HAS_BIAS && add_bias) { b0 = bias[nc]; b1 = bias[nc + 1]; }
            float v0 = acc[mt][nt][0] * alpha + b0;
            float v1 = acc[mt][nt][1] * alpha + b1;
            float v2 = acc[mt][nt][2] * alpha + b0;
            float v3 = acc[mt][nt][3] * alpha + b1;
            if (GELU) {
                v0 = 0.5f * v0 * (1.f + erff(v0 * 0.70710678118654752f));
                v1 = 0.5f * v1 * (1.f + erff(v1 * 0.70710678118654752f));
                v2 = 0.5f * v2 * (1.f + erff(v2 * 0.70710678118654752f));
                v3 = 0.5f * v3 * (1.f + erff(v3 * 0.70710678118654752f));
            }
            if (HALF_OUT) {
                uint32_t* Ch = (uint32_t*)Cp;
                Ch[((size_t)(mr + grp    ) * ldC + nc) >> 1] = h2u(v0, v1);
                Ch[((size_t)(mr + grp + 8) * ldC + nc) >> 1] = h2u(v2, v3);
            } else {
                float* Cf = (float*)Cp;
                *reinterpret_cast<float2*>(&Cf[(size_t)(mr + grp) * ldC + nc]) =
                    make_float2(v0, v1);
                *reinterpret_cast<float2*>(&Cf[(size_t)(mr + grp + 8) * ldC + nc]) =
                    make_float2(v2, v3);
            }
        }
    }
}

// ---------------------------------------------------------------------------
// fp16 flash attention (unchanged from R15): 128-thread CTAs (4 warps, 64 q),
// 16 queries/warp, register-resident P, exp2 softmax, l via pre-summed P +
// single ones-mma, V via ldmatrix.x4.trans, 3-stage cp.async, one sync/chunk.
// grid: (SEQ/64, HEADS, 2*BATCH) = 1024 CTAs.
// smem: K [3][64][40]h + V [3][64][40]h = 30720 B.
// ---------------------------------------------------------------------------
#define FLASH_SMEM ((3*64*40 + 3*64*40) * 2)

__global__ __launch_bounds__(128, 5) void flash_tc(
    const __half* __restrict__ qkb, const __half* __restrict__ vb,
    __half* __restrict__ mb)
{
    extern __shared__ __half dsm[];
    __half* KsB = dsm;                       // [3][64][40]
    __half* VsB = dsm + 3 * 64 * 40;         // [3][64][40]

    int tid = threadIdx.x;
    int wid = tid >> 5, lane = tid & 31;
    int grp = lane >> 2, tig = lane & 3;
    int lm = lane >> 3, lr = lane & 7;
    int h = blockIdx.y;
    int z = blockIdx.z;
    int b = z & 1, dir = z >> 1;

    const __half* Q  = dir ? qkb + STREAM_OFF : qkb;
    const __half* Kp = dir ? qkb : qkb + STREAM_OFF;
    const __half* Vp = dir ? vb  : vb  + STREAM_OFF;
    __half*       O  = dir ? mb + STREAM_OFF : mb;

    size_t brow = (size_t)b * SEQ;
    int q0 = blockIdx.x * 64 + wid * 16;

    // ldmatrix lane addressing
    int k_row = (lm >> 1) * 8 + lr;
    int k_col = (lm & 1) * 8;
    int v_row = (lm & 1) * 8 + lr;
    int v_col = (lm >> 1) * 8;

    // register-resident Q fragments: 2 k16-chunks over dh=32
    uint32_t qa[2][4];
    const uint32_t* Qu = reinterpret_cast<const uint32_t*>(
        Q + (brow + q0) * DIMC + h * HEAD_DIM);
#pragma unroll
    for (int kc = 0; kc < 2; kc++) {
        qa[kc][0] = Qu[(grp    ) * 128 + kc * 8 + tig    ];
        qa[kc][1] = Qu[(grp + 8) * 128 + kc * 8 + tig    ];
        qa[kc][2] = Qu[(grp    ) * 128 + kc * 8 + tig + 4];
        qa[kc][3] = Qu[(grp + 8) * 128 + kc * 8 + tig + 4];
    }

    auto load_chunk = [&](int kc, int s) {
        __half* Kd = KsB + s * (64 * 40);
        __half* Vd = VsB + s * (64 * 40);
#pragma unroll
        for (int j = 0; j < 2; j++) {
            int idx = tid + j * 128;
            int r = idx >> 2, c = idx & 3;
            size_t g = (brow + (size_t)kc * 64 + r) * DIMC + h * HEAD_DIM + c * 8;
            cp_async16(smem_u32(&Kd[r * 40 + c * 8]), Kp + g);
            cp_async16(smem_u32(&Vd[r * 40 + c * 8]), Vp + g);
        }
        cp_commit();
    };

    float oacc[4][4] = {};
    float lacc[4] = {};
    float mr0 = -1e30f, mr1 = -1e30f;
    constexpr int NC = SEQ / 64;

    load_chunk(0, 0);
    load_chunk(1, 1);

    int s = 0, sl = 2;
    for (int kc = 0; kc < NC; kc++) {
        if (kc + 1 < NC) cp_wait<1>();
        else             cp_wait<0>();
        __syncthreads();
        if (kc + 2 < NC) load_chunk(kc + 2, sl);

        const __half* Kd = KsB + s * (64 * 40);
        const __half* Vd = VsB + s * (64 * 40);

        // S = Q @ K^T : scores in log2 units
        float sf[8][4] = {};
#pragma unroll
        for (int kk = 0; kk < 2; kk++) {
            uint32_t bf[8][2];
#pragma unroll
            for (int p = 0; p < 4; p++) {
                uint32_t r0, r1, r2, r3;
                ldsm_x4(r0, r1, r2, r3,
                        smem_u32(Kd + (k_row + p * 16) * 40 + k_col + kk * 16));
                bf[2 * p][0] = r0; bf[2 * p][1] = r1;
                bf[2 * p + 1][0] = r2; bf[2 * p + 1][1] = r3;
            }
#pragma unroll
            for (int nt = 0; nt < 8; nt++)
                mma_f16(sf[nt][0], sf[nt][1], sf[nt][2], sf[nt][3],
                        qa[kk][0], qa[kk][1], qa[kk][2], qa[kk][3],
                        bf[nt][0], bf[nt][1]);
        }

        // online softmax (log2 domain)
        float cm0 = -1e30f, cm1 = -1e30f;
#pragma unroll
        for (int nt = 0; nt < 8; nt++) {
            cm0 = fmaxf(cm0, fmaxf(sf[nt][0], sf[nt][1]));
            cm1 = fmaxf(cm1, fmaxf(sf[nt][2], sf[nt][3]));
        }
        cm0 = fmaxf(cm0, __shfl_xor_sync(0xffffffffu, cm0, 1));
        cm0 = fmaxf(cm0, __shfl_xor_sync(0xffffffffu, cm0, 2));
        cm1 = fmaxf(cm1, __shfl_xor_sync(0xffffffffu, cm1, 1));
        cm1 = fmaxf(cm1, __shfl_xor_sync(0xffffffffu, cm1, 2));
        float nm0 = fmaxf(mr0, cm0), nm1 = fmaxf(mr1, cm1);
        float corr0 = exp2_f32(mr0 - nm0), corr1 = exp2_f32(mr1 - nm1);
        mr0 = nm0; mr1 = nm1;

        // P = exp2(s - m) straight into PV A-fragments
        uint32_t pa[4][4];
#pragma unroll
        for (int kk = 0; kk < 4; kk++) {
            pa[kk][0] = exp2_h2(sf[2*kk    ][0] - nm0, sf[2*kk    ][1] - nm0);
            pa[kk][1] = exp2_h2(sf[2*kk    ][2] - nm1, sf[2*kk    ][3] - nm1);
            pa[kk][2] = exp2_h2(sf[2*kk + 1][0] - nm0, sf[2*kk + 1][1] - nm0);
            pa[kk][3] = exp2_h2(sf[2*kk + 1][2] - nm1, sf[2*kk + 1][3] - nm1);
        }

        lacc[0] *= corr0; lacc[2] *= corr1;
#pragma unroll
        for (int nt = 0; nt < 4; nt++) {
            oacc[nt][0] *= corr0; oacc[nt][1] *= corr0;
            oacc[nt][2] *= corr1; oacc[nt][3] *= corr1;
        }

        // l: pre-sum P fragments across kk + single ones-mma
        {
            uint32_t ps0 = hadd2u(hadd2u(pa[0][0], pa[1][0]), hadd2u(pa[2][0], pa[3][0]));
            uint32_t ps1 = hadd2u(hadd2u(pa[0][1], pa[1][1]), hadd2u(pa[2][1], pa[3][1]));
            uint32_t ps2 = hadd2u(hadd2u(pa[0][2], pa[1][2]), hadd2u(pa[2][2], pa[3][2]));
            uint32_t ps3 = hadd2u(hadd2u(pa[0][3], pa[1][3]), hadd2u(pa[2][3], pa[3][3]));
            mma_f16(lacc[0], lacc[1], lacc[2], lacc[3],
                    ps0, ps1, ps2, ps3, ONES_H2, ONES_H2);
        }

        // O += P @ V
#pragma unroll
        for (int kk = 0; kk < 4; kk++) {
#pragma unroll
            for (int np = 0; np < 2; np++) {
                uint32_t b0, b1, b2, b3;
                ldsm_x4_trans(b0, b1, b2, b3,
                    smem_u32(Vd + (kk * 16 + v_row) * 40 + np * 16 + v_col));
                mma_f16(oacc[2*np][0], oacc[2*np][1], oacc[2*np][2], oacc[2*np][3],
                        pa[kk][0], pa[kk][1], pa[kk][2], pa[kk][3], b0, b1);
                mma_f16(oacc[2*np+1][0], oacc[2*np+1][1], oacc[2*np+1][2], oacc[2*np+1][3],
                        pa[kk][0], pa[kk][1], pa[kk][2], pa[kk][3], b2, b3);
            }
        }

        s = (s == 2) ? 0 : s + 1;
        sl = (sl == 2) ? 0 : sl + 1;
    }

    float inv0 = 1.f / lacc[0], inv1 = 1.f / lacc[2];
    uint32_t* Ou = reinterpret_cast<uint32_t*>(
        O + (brow + q0) * DIMC + h * HEAD_DIM);
#pragma unroll
    for (int nt = 0; nt < 4; nt++) {
        Ou[(grp    ) * 128 + nt * 4 + tig] =
            h2u(oacc[nt][0] * inv0, oacc[nt][1] * inv0);
        Ou[(grp + 8) * 128 + nt * 4 + tig] =
            h2u(oacc[nt][2] * inv1, oacc[nt][3] * inv1);
    }
}

// ---------------------------------------------------------------------------
// Launch
// ---------------------------------------------------------------------------
extern "C" void kernel_launch(void* const* d_in, const int* in_sizes, int n_in,
                              void* d_out, int out_size)
{
    const float* x0      = (const float*)d_in[0];
    const float* x1      = (const float*)d_in[1];
    const float* qk_w    = (const float*)d_in[2];
    const float* v_w     = (const float*)d_in[3];
    const float* merge_w = (const float*)d_in[4];
    const float* ln1_w   = (const float*)d_in[5];
    const float* ln1_b   = (const float*)d_in[6];
    const float* ln2_w   = (const float*)d_in[7];
    const float* ln2_b   = (const float*)d_in[8];
    const float* fc1_w   = (const float*)d_in[9];
    const float* fc1_b   = (const float*)d_in[10];
    const float* fc2_w   = (const float*)d_in[11];
    const float* fc2_b   = (const float*)d_in[12];
    const float* gamma   = (const float*)d_in[13];
    float* out = (float*)d_out;

    __half *nbuf, *qk, *v, *m, *cat, *h;
    __half *wqk, *wv, *wm, *wf1, *wf2;
    float *t, *t2;
    cudaGetSymbolAddress((void**)&nbuf, g_n);
    cudaGetSymbolAddress((void**)&qk,   g_qk);
    cudaGetSymbolAddress((void**)&v,    g_v);
    cudaGetSymbolAddress((void**)&m,    g_m);
    cudaGetSymbolAddress((void**)&cat,  g_cat);
    cudaGetSymbolAddress((void**)&h,    g_h);
    cudaGetSymbolAddress((void**)&t,    g_t);
    cudaGetSymbolAddress((void**)&t2,   g_t2);
    cudaGetSymbolAddress((void**)&wqk,  g_wqk);
    cudaGetSymbolAddress((void**)&wv,   g_wv);
    cudaGetSymbolAddress((void**)&wm,   g_wm);
    cudaGetSymbolAddress((void**)&wf1,  g_wf1);
    cudaGetSymbolAddress((void**)&wf2,  g_wf2);

    cudaFuncSetAttribute(gemm_tc<false, false, true, true, false>,
                         cudaFuncAttributeMaxDynamicSharedMemorySize, GEMM_SMEM);
    cudaFuncSetAttribute(gemm_tc<false, false, false, true, false>,
                         cudaFuncAttributeMaxDynamicSharedMemorySize, GEMM_SMEM);
    cudaFuncSetAttribute(gemm_tc<true, true, false, true, false>,
                         cudaFuncAttributeMaxDynamicSharedMemorySize, GEMM_SMEM);
    cudaFuncSetAttribute(gemm_tc<false, true, false, false, true>,
                         cudaFuncAttributeMaxDynamicSharedMemorySize, GEMM_SMEM);
    cudaFuncSetAttribute(flash_tc,
                         cudaFuncAttributeMaxDynamicSharedMemorySize, FLASH_SMEM);

    // 1. Fused weight-cvt + LayerNorm1 (also writes h(x) into cat[:,0:256])
    ln_cvt_kernel<<<CVT_BLOCKS + LN_BLOCKS, 256>>>(
        x0, x1, ln1_w, ln1_b, qk_w, v_w, merge_w, fc1_w, fc2_w, nbuf, cat);

    // 2. Fused qk+v projection; qk carries HEAD_DIM^-.25 * sqrt(log2 e)
    dim3 gP2(2 * DIMC / 128, TOTAL_ROWS / 128);
    gemm_tc<false, false, true, true, false><<<gP2, 256, GEMM_SMEM>>>(
        nbuf, wqk, wv, nullptr, qk, v, DIMC, DIMC, DIMC, QK_SCALE_L2, 1.f);

    // 3. Flash attention (128-thread CTAs, 1024 CTAs)
    dim3 gF(SEQ / 64, HEADS, 2 * BATCH);
    flash_tc<<<gF, 128, FLASH_SMEM>>>(qk, v, m);

    // 4. Merge projection -> cat[:,256:512] (ldC=512)
    dim3 gP(DIMC / 128, TOTAL_ROWS / 128);
    gemm_tc<false, false, false, true, false><<<gP, 256, GEMM_SMEM>>>(
        m, wm, nullptr, nullptr, cat + DIMC, nullptr,
        DIMC, DIMC, 2 * DIMC, 1.f, 1.f);

    // 5. fc1 + exact GELU (K=512 GEMM on cat)
    dim3 gF1(HIDDEN / 128, TOTAL_ROWS / 128);
    gemm_tc<true, true, false, true, false><<<gF1, 256, GEMM_SMEM>>>(
        cat, wf1, nullptr, fc1_b, h, nullptr,
        HIDDEN, 2 * DIMC, HIDDEN, 1.f, 1.f);

    // 6. fc2 split-K=2 (z=0 -> t with bias, z=1 -> t2), 256 CTAs
    dim3 gP3(DIMC / 128, TOTAL_ROWS / 128, 2);
    gemm_tc<false, true, false, false, true><<<gP3, 256, GEMM_SMEM>>>(
        h, wf2, nullptr, fc2_b, t, t2,
        DIMC, HIDDEN, DIMC, 1.f, 1.f);

    // 7. Residual + gamma * LN2(t + t2)
    final_kernel<<<TOTAL_ROWS / 8, 256>>>(t, t2, x0, x1, ln2_w, ln2_b, gamma, out);
}